// round 4
// baseline (speedup 1.0000x reference)
#include <cuda_runtime.h>
#include <cuda_bf16.h>
#include <math.h>
#include <stdint.h>

// Problem constants
#define Bc   8
#define Tc   2048
#define Cc   512
#define Hc   8
#define Nc   64
#define DMIX 32
#define DDEC 64
#define BT   (Bc*Tc)           // 16384
#define BTC  (BT*Cc)           // 8388608

// ---------------------------------------------------------------------------
// Scratch (static device globals; no allocation allowed)
// ---------------------------------------------------------------------------
__device__ float g_xx  [BTC];
__device__ float g_xxx [BTC];
__device__ float g_h   [BT*160];
__device__ float g_xw  [BTC];
__device__ float g_xk  [BTC];
__device__ float g_xv  [BTC];
__device__ float g_xr  [BTC];
__device__ float g_xg  [BTC];
__device__ float g_r   [BTC];
__device__ float g_k   [BTC];
__device__ float g_v   [BTC];
__device__ float g_gate[BTC];
__device__ float g_wp  [BT*DDEC];
__device__ float g_w   [BTC];
__device__ float g_y   [BTC];
__device__ float g_z   [BTC];
__device__ float g_w1t [256*512];   // W1^T padded 160->256 rows
__device__ float g_dw1t[128*512];   // dw1^T padded 64->128 rows
__device__ float g_dw2t[512*64];    // dw2^T [512][64]

// ---------------------------------------------------------------------------
// Elementwise: token shift + xxx = x + xx * maa_x
// ---------------------------------------------------------------------------
__global__ void ew_shift_mix(const float* __restrict__ x,
                             const float* __restrict__ maa_x,
                             float* __restrict__ xx, float* __restrict__ xxx)
{
    int idx = blockIdx.x * 256 + threadIdx.x;
    if (idx >= BTC) return;
    int c  = idx & (Cc - 1);
    int tg = idx >> 9;
    int tt = tg & (Tc - 1);
    float xi = x[idx];
    float xs = (tt > 0) ? x[idx - Cc] : 0.f;
    float xxv = xs - xi;
    xx[idx]  = xxv;
    xxx[idx] = fmaf(xxv, maa_x[c], xi);
}

// ---------------------------------------------------------------------------
// Weight transpose + zero-pad (tiny, once per call)
// ---------------------------------------------------------------------------
__global__ void transpose_pad(const float* __restrict__ W1,
                              const float* __restrict__ dw1,
                              const float* __restrict__ dw2,
                              float* __restrict__ w1t,
                              float* __restrict__ dw1t,
                              float* __restrict__ dw2t)
{
    int idx = blockIdx.x * 256 + threadIdx.x;
    if (idx < 256 * 512) {
        int n = idx >> 9, k = idx & 511;
        w1t[idx] = (n < 160) ? W1[k * 160 + n] : 0.f;
    } else if (idx < 256 * 512 + 128 * 512) {
        int j = idx - 256 * 512;
        int n = j >> 9, k = j & 511;
        dw1t[j] = (n < 64) ? dw1[k * 64 + n] : 0.f;
    } else if (idx < 256 * 512 + 128 * 512 + 512 * 64) {
        int j = idx - (256 * 512 + 128 * 512);
        int n = j >> 6, k = j & 63;
        dw2t[j] = dw2[k * 512 + n];
    }
}

// ---------------------------------------------------------------------------
// TF32 tensor-core GEMM body: C[M,Nreal] = epi( A[M,K] @ W[Npad,K]^T )
//   grid.x covers Npad/128 (W zero-padded beyond Nreal).
//   epi: 0 none, 1 tanh, 2 silu, 3 exp(-exp(bias[n]+v))
// ---------------------------------------------------------------------------
__device__ __forceinline__ uint32_t f2tf32(float x)
{
    uint32_t u;
    asm("cvt.rna.tf32.f32 %0, %1;" : "=r"(u) : "f"(x));
    return u;
}

__device__ __forceinline__ void tf32_body(const float* __restrict__ A,
                                          const float* __restrict__ W,
                                          float* __restrict__ Cm,
                                          const float* __restrict__ bias,
                                          int M, int K, int Nreal, int ldc, int epi)
{
    __shared__ float As[2][128][20];
    __shared__ float Bs[2][128][20];

    int tid  = threadIdx.x;
    int warp = tid >> 5, lane = tid & 31;
    int wm = (warp >> 2) * 64;
    int wn = (warp & 3) * 32;
    int gid = lane >> 2, tig = lane & 3;
    int m0 = blockIdx.y * 128, n0 = blockIdx.x * 128;

    int lr = tid >> 1;
    int lq = (tid & 1) * 2;
    const float* Aptr = A + (size_t)(m0 + lr) * K;
    const float* Wptr = W + (size_t)(n0 + lr) * K;

    float acc[4][4][4];
#pragma unroll
    for (int mt = 0; mt < 4; mt++)
#pragma unroll
        for (int nt = 0; nt < 4; nt++)
#pragma unroll
            for (int d = 0; d < 4; d++) acc[mt][nt][d] = 0.f;

    auto stage = [&](int buf, int k0) {
#pragma unroll
        for (int i = 0; i < 2; i++) {
            int kq = (lq + i) * 4;
            float4 av = *reinterpret_cast<const float4*>(Aptr + k0 + kq);
            av.x = __uint_as_float(f2tf32(av.x));
            av.y = __uint_as_float(f2tf32(av.y));
            av.z = __uint_as_float(f2tf32(av.z));
            av.w = __uint_as_float(f2tf32(av.w));
            *reinterpret_cast<float4*>(&As[buf][lr][kq]) = av;
            float4 bv = *reinterpret_cast<const float4*>(Wptr + k0 + kq);
            bv.x = __uint_as_float(f2tf32(bv.x));
            bv.y = __uint_as_float(f2tf32(bv.y));
            bv.z = __uint_as_float(f2tf32(bv.z));
            bv.w = __uint_as_float(f2tf32(bv.w));
            *reinterpret_cast<float4*>(&Bs[buf][lr][kq]) = bv;
        }
    };

    stage(0, 0);
    __syncthreads();

    for (int k0 = 0; k0 < K; k0 += 16) {
        int buf = (k0 >> 4) & 1;
        if (k0 + 16 < K) stage(buf ^ 1, k0 + 16);

#pragma unroll
        for (int ks = 0; ks < 2; ks++) {
            int kb = ks * 8;
            uint32_t afr[4][4];
#pragma unroll
            for (int mt = 0; mt < 4; mt++) {
                int m = wm + mt * 16;
                afr[mt][0] = __float_as_uint(As[buf][m + gid    ][kb + tig    ]);
                afr[mt][1] = __float_as_uint(As[buf][m + gid + 8][kb + tig    ]);
                afr[mt][2] = __float_as_uint(As[buf][m + gid    ][kb + tig + 4]);
                afr[mt][3] = __float_as_uint(As[buf][m + gid + 8][kb + tig + 4]);
            }
            uint32_t bfr[4][2];
#pragma unroll
            for (int nt = 0; nt < 4; nt++) {
                int n = wn + nt * 8;
                bfr[nt][0] = __float_as_uint(Bs[buf][n + gid][kb + tig    ]);
                bfr[nt][1] = __float_as_uint(Bs[buf][n + gid][kb + tig + 4]);
            }
#pragma unroll
            for (int mt = 0; mt < 4; mt++)
#pragma unroll
                for (int nt = 0; nt < 4; nt++) {
                    asm volatile(
                        "mma.sync.aligned.m16n8k8.row.col.f32.tf32.tf32.f32 "
                        "{%0,%1,%2,%3}, {%4,%5,%6,%7}, {%8,%9}, {%0,%1,%2,%3};"
                        : "+f"(acc[mt][nt][0]), "+f"(acc[mt][nt][1]),
                          "+f"(acc[mt][nt][2]), "+f"(acc[mt][nt][3])
                        : "r"(afr[mt][0]), "r"(afr[mt][1]),
                          "r"(afr[mt][2]), "r"(afr[mt][3]),
                          "r"(bfr[nt][0]), "r"(bfr[nt][1]));
                }
        }
        __syncthreads();
    }

#pragma unroll
    for (int mt = 0; mt < 4; mt++) {
        int m = m0 + wm + mt * 16 + gid;
#pragma unroll
        for (int nt = 0; nt < 4; nt++) {
            int gb = n0 + wn + nt * 8;       // 8-col group base; Nreal % 8 == 0
            if (gb >= Nreal) continue;
            int n = gb + 2 * tig;
            float v0 = acc[mt][nt][0], v1 = acc[mt][nt][1];
            float v2 = acc[mt][nt][2], v3 = acc[mt][nt][3];
            if (epi == 1) {
                v0 = tanhf(v0); v1 = tanhf(v1); v2 = tanhf(v2); v3 = tanhf(v3);
            } else if (epi == 2) {
                v0 = v0 / (1.f + expf(-v0));
                v1 = v1 / (1.f + expf(-v1));
                v2 = v2 / (1.f + expf(-v2));
                v3 = v3 / (1.f + expf(-v3));
            } else if (epi == 3) {
                float b0 = bias[n], b1 = bias[n + 1];
                v0 = expf(-expf(b0 + v0));
                v1 = expf(-expf(b1 + v1));
                v2 = expf(-expf(b0 + v2));
                v3 = expf(-expf(b1 + v3));
            }
            *reinterpret_cast<float2*>(&Cm[(size_t)m * ldc + n])       = make_float2(v0, v1);
            *reinterpret_cast<float2*>(&Cm[(size_t)(m + 8) * ldc + n]) = make_float2(v2, v3);
        }
    }
}

__global__ __launch_bounds__(256)
void tf32_gemm(const float* __restrict__ A, const float* __restrict__ W,
               float* __restrict__ C, const float* __restrict__ bias,
               int M, int K, int Nreal, int ldc, int epi)
{
    tf32_body(A, W, C, bias, M, K, Nreal, ldc, epi);
}

// 4 projections in one launch (blockIdx.z selects)
__global__ __launch_bounds__(256)
void proj4_kernel(const float* __restrict__ xr, const float* __restrict__ xk,
                  const float* __restrict__ xv, const float* __restrict__ xg,
                  const float* __restrict__ Wr, const float* __restrict__ Wk,
                  const float* __restrict__ Wv, const float* __restrict__ Wg,
                  float* __restrict__ r, float* __restrict__ k,
                  float* __restrict__ v, float* __restrict__ g)
{
    const float* A; const float* W; float* C; int epi = 0;
    int z = blockIdx.z;
    if      (z == 0) { A = xr; W = Wr; C = r; }
    else if (z == 1) { A = xk; W = Wk; C = k; }
    else if (z == 2) { A = xv; W = Wv; C = v; }
    else             { A = xg; W = Wg; C = g; epi = 2; }
    tf32_body(A, W, C, nullptr, BT, Cc, Cc, Cc, epi);
}

// ---------------------------------------------------------------------------
// Fused 5-way mix GEMM:
//   for f in 0..4:  out_f = x + xx * (maa_f + h[:, f*32:(f+1)*32] @ W2[f])
//   h: [BT,160], W2: [5,32,512].  64x64 tile, K=32 per f.
// ---------------------------------------------------------------------------
__global__ __launch_bounds__(256)
void mix5_kernel(const float* __restrict__ hsrc, const float* __restrict__ W2,
                 const float* __restrict__ m0p, const float* __restrict__ m1p,
                 const float* __restrict__ m2p, const float* __restrict__ m3p,
                 const float* __restrict__ m4p,
                 const float* __restrict__ x, const float* __restrict__ xx,
                 float* __restrict__ o0, float* __restrict__ o1,
                 float* __restrict__ o2, float* __restrict__ o3,
                 float* __restrict__ o4)
{
    __shared__ float As[32][68];
    __shared__ float Bs[32][68];

    int tid = threadIdx.x;
    int tx = tid & 15, ty = tid >> 4;
    int m0 = blockIdx.y * 64;
    int n0 = blockIdx.x * 64;

    float acc[5][4][4];
#pragma unroll
    for (int f = 0; f < 5; f++)
#pragma unroll
        for (int i = 0; i < 4; i++)
#pragma unroll
            for (int j = 0; j < 4; j++) acc[f][i][j] = 0.f;

    int arow = tid >> 2;                 // 0..63
    int aq   = (tid & 3) * 2;            // float4 slot base (2 per thread)
    int brow = tid >> 3;                 // 0..31
    int bq   = (tid & 7) * 8;            // col base (2 float4 per thread)

    for (int f = 0; f < 5; f++) {
        __syncthreads();
        // stage A: h[m0+arow][f*32 + cols]
        {
            const float* ap = hsrc + (size_t)(m0 + arow) * 160 + f * 32;
#pragma unroll
            for (int i = 0; i < 2; i++) {
                int col = (aq + i) * 4;
                float4 av = *reinterpret_cast<const float4*>(ap + col);
                As[col + 0][arow] = av.x;
                As[col + 1][arow] = av.y;
                As[col + 2][arow] = av.z;
                As[col + 3][arow] = av.w;
            }
        }
        // stage B: W2[f][brow][n0+bq..]
        {
            const float* bp = W2 + (size_t)f * 32 * Cc + (size_t)brow * Cc + n0 + bq;
            *reinterpret_cast<float4*>(&Bs[brow][bq])     = *reinterpret_cast<const float4*>(bp);
            *reinterpret_cast<float4*>(&Bs[brow][bq + 4]) = *reinterpret_cast<const float4*>(bp + 4);
        }
        __syncthreads();

#pragma unroll
        for (int kk = 0; kk < 32; kk++) {
            float4 a4 = *reinterpret_cast<const float4*>(&As[kk][ty * 4]);
            float4 b4 = *reinterpret_cast<const float4*>(&Bs[kk][tx * 4]);
            float ar[4] = {a4.x, a4.y, a4.z, a4.w};
            float br[4] = {b4.x, b4.y, b4.z, b4.w};
#pragma unroll
            for (int i = 0; i < 4; i++)
#pragma unroll
                for (int j = 0; j < 4; j++)
                    acc[f][i][j] = fmaf(ar[i], br[j], acc[f][i][j]);
        }
    }

    // epilogue
    int nb = n0 + tx * 4;
    float4 ma[5];
    ma[0] = *reinterpret_cast<const float4*>(m0p + nb);
    ma[1] = *reinterpret_cast<const float4*>(m1p + nb);
    ma[2] = *reinterpret_cast<const float4*>(m2p + nb);
    ma[3] = *reinterpret_cast<const float4*>(m3p + nb);
    ma[4] = *reinterpret_cast<const float4*>(m4p + nb);
    float* outs[5] = {o0, o1, o2, o3, o4};

#pragma unroll
    for (int i = 0; i < 4; i++) {
        size_t base = (size_t)(m0 + ty * 4 + i) * Cc + nb;
        float4 xv  = *reinterpret_cast<const float4*>(x + base);
        float4 xxv = *reinterpret_cast<const float4*>(xx + base);
#pragma unroll
        for (int f = 0; f < 5; f++) {
            float4 o;
            o.x = fmaf(xxv.x, ma[f].x + acc[f][i][0], xv.x);
            o.y = fmaf(xxv.y, ma[f].y + acc[f][i][1], xv.y);
            o.z = fmaf(xxv.z, ma[f].z + acc[f][i][2], xv.z);
            o.w = fmaf(xxv.w, ma[f].w + acc[f][i][3], xv.w);
            *reinterpret_cast<float4*>(outs[f] + base) = o;
        }
    }
}

// ---------------------------------------------------------------------------
// WKV6 linear recurrence. 128 blocks: (b, h, i-half). 256 threads = 8 warps.
// Warp q owns state rows j in [q*8, q*8+8); lane = local output index i (32).
// ---------------------------------------------------------------------------
__global__ __launch_bounds__(256)
void wkv_kernel(const float* __restrict__ r, const float* __restrict__ k,
                const float* __restrict__ v, const float* __restrict__ w,
                const float* __restrict__ u, float* __restrict__ y)
{
    int bid  = blockIdx.x;
    int ih   = bid & 1;
    int h    = (bid >> 1) & 7;
    int b    = bid >> 4;
    int tid  = threadIdx.x;
    int lane = tid & 31;
    int warp = tid >> 5;
    int role = tid >> 6;           // 0..3
    int gi   = tid & 63;

    __shared__ float sr[64], sk[64], sw[64], sv[32];
    __shared__ float part[8][32];

    float S[8];
#pragma unroll
    for (int jj = 0; jj < 8; jj++) S[jj] = 0.f;

    float uu[8];
#pragma unroll
    for (int jj = 0; jj < 8; jj++) uu[jj] = u[h * 64 + warp * 8 + jj];

    int hbase = h * 64;
    size_t base = (size_t)(b * Tc) * Cc + hbase;

    // prefetch t=0
    float pf = 0.f;
    if      (role == 0) pf = r[base + gi];
    else if (role == 1) pf = k[base + gi];
    else if (role == 2) pf = w[base + gi];
    else if (gi < 32)   pf = v[base + ih * 32 + gi];

    for (int t = 0; t < Tc; t++) {
        if      (role == 0) sr[gi] = pf;
        else if (role == 1) sk[gi] = pf;
        else if (role == 2) sw[gi] = pf;
        else if (gi < 32)   sv[gi] = pf;
        __syncthreads();

        if (t + 1 < Tc) {
            size_t nb = base + Cc;
            if      (role == 0) pf = r[nb + gi];
            else if (role == 1) pf = k[nb + gi];
            else if (role == 2) pf = w[nb + gi];
            else if (gi < 32)   pf = v[nb + ih * 32 + gi];
        }

        float vi = sv[lane];
        float y0 = 0.f, y1 = 0.f;
#pragma unroll
        for (int jj = 0; jj < 8; jj++) {
            int j = warp * 8 + jj;
            float kv  = sk[j] * vi;
            float acc = fmaf(uu[jj], kv, S[jj]);
            if (jj & 1) y1 = fmaf(sr[j], acc, y1);
            else        y0 = fmaf(sr[j], acc, y0);
            S[jj] = fmaf(sw[j], S[jj], kv);
        }
        part[warp][lane] = y0 + y1;
        __syncthreads();

        if (tid < 32) {
            float yv = (part[0][tid] + part[1][tid]) + (part[2][tid] + part[3][tid])
                     + (part[4][tid] + part[5][tid]) + (part[6][tid] + part[7][tid]);
            y[base + ih * 32 + tid] = yv;
        }
        base += Cc;
    }
}

// ---------------------------------------------------------------------------
// GroupNorm (H groups of N=64) + ln scale/shift + gate multiply
// ---------------------------------------------------------------------------
__global__ __launch_bounds__(256)
void gn_kernel(const float* __restrict__ y, const float* __restrict__ gsrc,
               const float* __restrict__ lng, const float* __restrict__ lnb,
               float* __restrict__ z)
{
    int warp = threadIdx.x >> 5, lane = threadIdx.x & 31;
    int grp = blockIdx.x * 8 + warp;           // < BT*H
    int tg = grp >> 3, h = grp & 7;
    size_t base = (size_t)tg * Cc + h * 64;

    float y0 = y[base + lane];
    float y1 = y[base + 32 + lane];
    float s  = y0 + y1;
    float ss = y0 * y0 + y1 * y1;
#pragma unroll
    for (int o = 16; o; o >>= 1) {
        s  += __shfl_xor_sync(0xffffffffu, s, o);
        ss += __shfl_xor_sync(0xffffffffu, ss, o);
    }
    float mean = s * (1.f / 64.f);
    float var  = ss * (1.f / 64.f) - mean * mean;
    float rstd = rsqrtf(var + 1e-5f);

    int c0 = h * 64 + lane;
    float z0 = fmaf((y0 - mean) * rstd, lng[c0],      lnb[c0]);
    float z1 = fmaf((y1 - mean) * rstd, lng[c0 + 32], lnb[c0 + 32]);
    z[base + lane]      = z0 * gsrc[base + lane];
    z[base + 32 + lane] = z1 * gsrc[base + 32 + lane];
}

// ---------------------------------------------------------------------------
// Launch
// ---------------------------------------------------------------------------
template <typename T>
static float* devptr(T& sym)
{
    void* p = nullptr;
    cudaGetSymbolAddress(&p, sym);
    return (float*)p;
}

extern "C" void kernel_launch(void* const* d_in, const int* in_sizes, int n_in,
                              void* d_out, int out_size)
{
    const float* x      = (const float*)d_in[0];
    const float* maa_x  = (const float*)d_in[1];
    const float* maa_w  = (const float*)d_in[2];
    const float* maa_k  = (const float*)d_in[3];
    const float* maa_v  = (const float*)d_in[4];
    const float* maa_r  = (const float*)d_in[5];
    const float* maa_g  = (const float*)d_in[6];
    const float* W1     = (const float*)d_in[7];   // [512,160]
    const float* W2     = (const float*)d_in[8];   // [5,32,512]
    const float* tdec   = (const float*)d_in[9];   // [512]
    const float* dw1    = (const float*)d_in[10];  // [512,64]
    const float* dw2    = (const float*)d_in[11];  // [64,512]
    const float* faaaa  = (const float*)d_in[12];  // [8,64]
    const float* Wr     = (const float*)d_in[13];
    const float* Wk     = (const float*)d_in[14];
    const float* Wv     = (const float*)d_in[15];
    const float* Wg     = (const float*)d_in[16];
    const float* Wo     = (const float*)d_in[17];
    const float* ln_g   = (const float*)d_in[18];
    const float* ln_b   = (const float*)d_in[19];
    float* out = (float*)d_out;

    float* p_xx   = devptr(g_xx);
    float* p_xxx  = devptr(g_xxx);
    float* p_h    = devptr(g_h);
    float* p_xw   = devptr(g_xw);
    float* p_xk   = devptr(g_xk);
    float* p_xv   = devptr(g_xv);
    float* p_xr   = devptr(g_xr);
    float* p_xg   = devptr(g_xg);
    float* p_r    = devptr(g_r);
    float* p_k    = devptr(g_k);
    float* p_v    = devptr(g_v);
    float* p_gate = devptr(g_gate);
    float* p_wp   = devptr(g_wp);
    float* p_w    = devptr(g_w);
    float* p_y    = devptr(g_y);
    float* p_z    = devptr(g_z);
    float* p_w1t  = devptr(g_w1t);
    float* p_dw1t = devptr(g_dw1t);
    float* p_dw2t = devptr(g_dw2t);

    const int ewGrid = (BTC + 255) / 256;

    // 0) weight transposes (tiny)
    transpose_pad<<<(256*512 + 128*512 + 512*64) / 256, 256>>>(
        W1, dw1, dw2, p_w1t, p_dw1t, p_dw2t);

    // 1) token shift + xxx
    ew_shift_mix<<<ewGrid, 256>>>(x, maa_x, p_xx, p_xxx);

    // 2) h = tanh(xxx @ W1)   [16384,160]  (tf32, N padded to 256)
    {
        dim3 grid(2, BT / 128);
        tf32_gemm<<<grid, 256>>>(p_xxx, p_w1t, p_h, nullptr, BT, Cc, 160, 160, 1);
    }
    // 3) fused: x_f = x + xx*(maa_f + h[:,f] @ W2[f]) for f in {w,k,v,r,g}
    {
        dim3 grid(Cc / 64, BT / 64);
        mix5_kernel<<<grid, 256>>>(p_h, W2, maa_w, maa_k, maa_v, maa_r, maa_g,
                                   x, p_xx, p_xw, p_xk, p_xv, p_xr, p_xg);
    }

    // 4) projections r, k, v, g  (tf32, batched single launch)
    {
        dim3 grid(Cc / 128, BT / 128, 4);
        proj4_kernel<<<grid, 256>>>(p_xr, p_xk, p_xv, p_xg,
                                    Wr, Wk, Wv, Wg,
                                    p_r, p_k, p_v, p_gate);
    }
    // 5) decay path (tf32): wp = tanh(xw @ dw1);  w = exp(-exp(tdec + wp @ dw2))
    {
        dim3 grid1(1, BT / 128);
        tf32_gemm<<<grid1, 256>>>(p_xw, p_dw1t, p_wp, nullptr, BT, Cc, 64, 64, 1);
        dim3 grid2(4, BT / 128);
        tf32_gemm<<<grid2, 256>>>(p_wp, p_dw2t, p_w, tdec, BT, 64, Cc, Cc, 3);
    }

    // 6) WKV6 recurrence
    wkv_kernel<<<Bc * Hc * 2, 256>>>(p_r, p_k, p_v, p_w, faaaa, p_y);

    // 7) GroupNorm + gate
    gn_kernel<<<(BT * Hc) / 8, 256>>>(p_y, p_gate, ln_g, ln_b, p_z);

    // 8) out = z @ Wo^T  (tf32)
    {
        dim3 grid(4, BT / 128);
        tf32_gemm<<<grid, 256>>>(p_z, Wo, out, nullptr, BT, Cc, Cc, Cc, 0);
    }
}

// round 5
// speedup vs baseline: 1.6171x; 1.6171x over previous
#include <cuda_runtime.h>
#include <cuda_bf16.h>
#include <math.h>
#include <stdint.h>

// Problem constants
#define Bc   8
#define Tc   2048
#define Cc   512
#define Hc   8
#define Nc   64
#define DMIX 32
#define DDEC 64
#define BT   (Bc*Tc)           // 16384
#define BTC  (BT*Cc)           // 8388608

// ---------------------------------------------------------------------------
// Scratch (static device globals; no allocation allowed)
// ---------------------------------------------------------------------------
__device__ float g_xx  [BTC];
__device__ float g_xxx [BTC];
__device__ float g_h   [BT*160];
__device__ float g_xw  [BTC];
__device__ float g_xk  [BTC];
__device__ float g_xv  [BTC];
__device__ float g_xr  [BTC];
__device__ float g_xg  [BTC];
__device__ float g_r   [BTC];
__device__ float g_k   [BTC];
__device__ float g_v   [BTC];
__device__ float g_gate[BTC];
__device__ float g_wp  [BT*DDEC];
__device__ float g_w   [BTC];
__device__ float g_y   [BTC];
__device__ float g_z   [BTC];
__device__ float g_w1t [256*512];   // W1^T padded 160->256 rows
__device__ float g_dw1t[128*512];   // dw1^T padded 64->128 rows
__device__ float g_dw2t[512*64];    // dw2^T [512][64]

// ---------------------------------------------------------------------------
// Elementwise: token shift + xxx = x + xx * maa_x
// ---------------------------------------------------------------------------
__global__ void ew_shift_mix(const float* __restrict__ x,
                             const float* __restrict__ maa_x,
                             float* __restrict__ xx, float* __restrict__ xxx)
{
    int idx = blockIdx.x * 256 + threadIdx.x;
    if (idx >= BTC) return;
    int c  = idx & (Cc - 1);
    int tg = idx >> 9;
    int tt = tg & (Tc - 1);
    float xi = x[idx];
    float xs = (tt > 0) ? x[idx - Cc] : 0.f;
    float xxv = xs - xi;
    xx[idx]  = xxv;
    xxx[idx] = fmaf(xxv, maa_x[c], xi);
}

// ---------------------------------------------------------------------------
// Weight transpose + zero-pad (tiny, once per call)
// ---------------------------------------------------------------------------
__global__ void transpose_pad(const float* __restrict__ W1,
                              const float* __restrict__ dw1,
                              const float* __restrict__ dw2,
                              float* __restrict__ w1t,
                              float* __restrict__ dw1t,
                              float* __restrict__ dw2t)
{
    int idx = blockIdx.x * 256 + threadIdx.x;
    if (idx < 256 * 512) {
        int n = idx >> 9, k = idx & 511;
        w1t[idx] = (n < 160) ? W1[k * 160 + n] : 0.f;
    } else if (idx < 256 * 512 + 128 * 512) {
        int j = idx - 256 * 512;
        int n = j >> 9, k = j & 511;
        dw1t[j] = (n < 64) ? dw1[k * 64 + n] : 0.f;
    } else if (idx < 256 * 512 + 128 * 512 + 512 * 64) {
        int j = idx - (256 * 512 + 128 * 512);
        int n = j >> 6, k = j & 63;
        dw2t[j] = dw2[k * 512 + n];
    }
}

// ---------------------------------------------------------------------------
// TF32 tensor-core GEMM body: C[M,Nreal] = epi( A[M,K] @ W[Npad,K]^T )
//   epi: 0 none, 1 tanh, 2 silu, 3 exp(-exp(bias[n]+v))
// ---------------------------------------------------------------------------
__device__ __forceinline__ uint32_t f2tf32(float x)
{
    uint32_t u;
    asm("cvt.rna.tf32.f32 %0, %1;" : "=r"(u) : "f"(x));
    return u;
}

__device__ __forceinline__ void tf32_body(const float* __restrict__ A,
                                          const float* __restrict__ W,
                                          float* __restrict__ Cm,
                                          const float* __restrict__ bias,
                                          int M, int K, int Nreal, int ldc, int epi)
{
    __shared__ float As[2][128][20];
    __shared__ float Bs[2][128][20];

    int tid  = threadIdx.x;
    int warp = tid >> 5, lane = tid & 31;
    int wm = (warp >> 2) * 64;
    int wn = (warp & 3) * 32;
    int gid = lane >> 2, tig = lane & 3;
    int m0 = blockIdx.y * 128, n0 = blockIdx.x * 128;

    int lr = tid >> 1;
    int lq = (tid & 1) * 2;
    const float* Aptr = A + (size_t)(m0 + lr) * K;
    const float* Wptr = W + (size_t)(n0 + lr) * K;

    float acc[4][4][4];
#pragma unroll
    for (int mt = 0; mt < 4; mt++)
#pragma unroll
        for (int nt = 0; nt < 4; nt++)
#pragma unroll
            for (int d = 0; d < 4; d++) acc[mt][nt][d] = 0.f;

    auto stage = [&](int buf, int k0) {
#pragma unroll
        for (int i = 0; i < 2; i++) {
            int kq = (lq + i) * 4;
            float4 av = *reinterpret_cast<const float4*>(Aptr + k0 + kq);
            av.x = __uint_as_float(f2tf32(av.x));
            av.y = __uint_as_float(f2tf32(av.y));
            av.z = __uint_as_float(f2tf32(av.z));
            av.w = __uint_as_float(f2tf32(av.w));
            *reinterpret_cast<float4*>(&As[buf][lr][kq]) = av;
            float4 bv = *reinterpret_cast<const float4*>(Wptr + k0 + kq);
            bv.x = __uint_as_float(f2tf32(bv.x));
            bv.y = __uint_as_float(f2tf32(bv.y));
            bv.z = __uint_as_float(f2tf32(bv.z));
            bv.w = __uint_as_float(f2tf32(bv.w));
            *reinterpret_cast<float4*>(&Bs[buf][lr][kq]) = bv;
        }
    };

    stage(0, 0);
    __syncthreads();

    for (int k0 = 0; k0 < K; k0 += 16) {
        int buf = (k0 >> 4) & 1;
        if (k0 + 16 < K) stage(buf ^ 1, k0 + 16);

#pragma unroll
        for (int ks = 0; ks < 2; ks++) {
            int kb = ks * 8;
            uint32_t afr[4][4];
#pragma unroll
            for (int mt = 0; mt < 4; mt++) {
                int m = wm + mt * 16;
                afr[mt][0] = __float_as_uint(As[buf][m + gid    ][kb + tig    ]);
                afr[mt][1] = __float_as_uint(As[buf][m + gid + 8][kb + tig    ]);
                afr[mt][2] = __float_as_uint(As[buf][m + gid    ][kb + tig + 4]);
                afr[mt][3] = __float_as_uint(As[buf][m + gid + 8][kb + tig + 4]);
            }
            uint32_t bfr[4][2];
#pragma unroll
            for (int nt = 0; nt < 4; nt++) {
                int n = wn + nt * 8;
                bfr[nt][0] = __float_as_uint(Bs[buf][n + gid][kb + tig    ]);
                bfr[nt][1] = __float_as_uint(Bs[buf][n + gid][kb + tig + 4]);
            }
#pragma unroll
            for (int mt = 0; mt < 4; mt++)
#pragma unroll
                for (int nt = 0; nt < 4; nt++) {
                    asm volatile(
                        "mma.sync.aligned.m16n8k8.row.col.f32.tf32.tf32.f32 "
                        "{%0,%1,%2,%3}, {%4,%5,%6,%7}, {%8,%9}, {%0,%1,%2,%3};"
                        : "+f"(acc[mt][nt][0]), "+f"(acc[mt][nt][1]),
                          "+f"(acc[mt][nt][2]), "+f"(acc[mt][nt][3])
                        : "r"(afr[mt][0]), "r"(afr[mt][1]),
                          "r"(afr[mt][2]), "r"(afr[mt][3]),
                          "r"(bfr[nt][0]), "r"(bfr[nt][1]));
                }
        }
        __syncthreads();
    }

#pragma unroll
    for (int mt = 0; mt < 4; mt++) {
        int m = m0 + wm + mt * 16 + gid;
#pragma unroll
        for (int nt = 0; nt < 4; nt++) {
            int gb = n0 + wn + nt * 8;       // 8-col group base; Nreal % 8 == 0
            if (gb >= Nreal) continue;
            int n = gb + 2 * tig;
            float v0 = acc[mt][nt][0], v1 = acc[mt][nt][1];
            float v2 = acc[mt][nt][2], v3 = acc[mt][nt][3];
            if (epi == 1) {
                v0 = tanhf(v0); v1 = tanhf(v1); v2 = tanhf(v2); v3 = tanhf(v3);
            } else if (epi == 2) {
                v0 = v0 / (1.f + expf(-v0));
                v1 = v1 / (1.f + expf(-v1));
                v2 = v2 / (1.f + expf(-v2));
                v3 = v3 / (1.f + expf(-v3));
            } else if (epi == 3) {
                float b0 = bias[n], b1 = bias[n + 1];
                v0 = expf(-expf(b0 + v0));
                v1 = expf(-expf(b1 + v1));
                v2 = expf(-expf(b0 + v2));
                v3 = expf(-expf(b1 + v3));
            }
            *reinterpret_cast<float2*>(&Cm[(size_t)m * ldc + n])       = make_float2(v0, v1);
            *reinterpret_cast<float2*>(&Cm[(size_t)(m + 8) * ldc + n]) = make_float2(v2, v3);
        }
    }
}

__global__ __launch_bounds__(256)
void tf32_gemm(const float* __restrict__ A, const float* __restrict__ W,
               float* __restrict__ C, const float* __restrict__ bias,
               int M, int K, int Nreal, int ldc, int epi)
{
    tf32_body(A, W, C, bias, M, K, Nreal, ldc, epi);
}

// 4 projections in one launch (blockIdx.z selects)
__global__ __launch_bounds__(256)
void proj4_kernel(const float* __restrict__ xr, const float* __restrict__ xk,
                  const float* __restrict__ xv, const float* __restrict__ xg,
                  const float* __restrict__ Wr, const float* __restrict__ Wk,
                  const float* __restrict__ Wv, const float* __restrict__ Wg,
                  float* __restrict__ r, float* __restrict__ k,
                  float* __restrict__ v, float* __restrict__ g)
{
    const float* A; const float* W; float* C; int epi = 0;
    int z = blockIdx.z;
    if      (z == 0) { A = xr; W = Wr; C = r; }
    else if (z == 1) { A = xk; W = Wk; C = k; }
    else if (z == 2) { A = xv; W = Wv; C = v; }
    else             { A = xg; W = Wg; C = g; epi = 2; }
    tf32_body(A, W, C, nullptr, BT, Cc, Cc, Cc, epi);
}

// ---------------------------------------------------------------------------
// Fused 5-way mix GEMM (unchanged from round 4)
// ---------------------------------------------------------------------------
__global__ __launch_bounds__(256)
void mix5_kernel(const float* __restrict__ hsrc, const float* __restrict__ W2,
                 const float* __restrict__ m0p, const float* __restrict__ m1p,
                 const float* __restrict__ m2p, const float* __restrict__ m3p,
                 const float* __restrict__ m4p,
                 const float* __restrict__ x, const float* __restrict__ xx,
                 float* __restrict__ o0, float* __restrict__ o1,
                 float* __restrict__ o2, float* __restrict__ o3,
                 float* __restrict__ o4)
{
    __shared__ float As[32][68];
    __shared__ float Bs[32][68];

    int tid = threadIdx.x;
    int tx = tid & 15, ty = tid >> 4;
    int m0 = blockIdx.y * 64;
    int n0 = blockIdx.x * 64;

    float acc[5][4][4];
#pragma unroll
    for (int f = 0; f < 5; f++)
#pragma unroll
        for (int i = 0; i < 4; i++)
#pragma unroll
            for (int j = 0; j < 4; j++) acc[f][i][j] = 0.f;

    int arow = tid >> 2;
    int aq   = (tid & 3) * 2;
    int brow = tid >> 3;
    int bq   = (tid & 7) * 8;

    for (int f = 0; f < 5; f++) {
        __syncthreads();
        {
            const float* ap = hsrc + (size_t)(m0 + arow) * 160 + f * 32;
#pragma unroll
            for (int i = 0; i < 2; i++) {
                int col = (aq + i) * 4;
                float4 av = *reinterpret_cast<const float4*>(ap + col);
                As[col + 0][arow] = av.x;
                As[col + 1][arow] = av.y;
                As[col + 2][arow] = av.z;
                As[col + 3][arow] = av.w;
            }
        }
        {
            const float* bp = W2 + (size_t)f * 32 * Cc + (size_t)brow * Cc + n0 + bq;
            *reinterpret_cast<float4*>(&Bs[brow][bq])     = *reinterpret_cast<const float4*>(bp);
            *reinterpret_cast<float4*>(&Bs[brow][bq + 4]) = *reinterpret_cast<const float4*>(bp + 4);
        }
        __syncthreads();

#pragma unroll
        for (int kk = 0; kk < 32; kk++) {
            float4 a4 = *reinterpret_cast<const float4*>(&As[kk][ty * 4]);
            float4 b4 = *reinterpret_cast<const float4*>(&Bs[kk][tx * 4]);
            float ar[4] = {a4.x, a4.y, a4.z, a4.w};
            float br[4] = {b4.x, b4.y, b4.z, b4.w};
#pragma unroll
            for (int i = 0; i < 4; i++)
#pragma unroll
                for (int j = 0; j < 4; j++)
                    acc[f][i][j] = fmaf(ar[i], br[j], acc[f][i][j]);
        }
    }

    int nb = n0 + tx * 4;
    float4 ma[5];
    ma[0] = *reinterpret_cast<const float4*>(m0p + nb);
    ma[1] = *reinterpret_cast<const float4*>(m1p + nb);
    ma[2] = *reinterpret_cast<const float4*>(m2p + nb);
    ma[3] = *reinterpret_cast<const float4*>(m3p + nb);
    ma[4] = *reinterpret_cast<const float4*>(m4p + nb);
    float* outs[5] = {o0, o1, o2, o3, o4};

#pragma unroll
    for (int i = 0; i < 4; i++) {
        size_t base = (size_t)(m0 + ty * 4 + i) * Cc + nb;
        float4 xv  = *reinterpret_cast<const float4*>(x + base);
        float4 xxv = *reinterpret_cast<const float4*>(xx + base);
#pragma unroll
        for (int f = 0; f < 5; f++) {
            float4 o;
            o.x = fmaf(xxv.x, ma[f].x + acc[f][i][0], xv.x);
            o.y = fmaf(xxv.y, ma[f].y + acc[f][i][1], xv.y);
            o.z = fmaf(xxv.z, ma[f].z + acc[f][i][2], xv.z);
            o.w = fmaf(xxv.w, ma[f].w + acc[f][i][3], xv.w);
            *reinterpret_cast<float4*>(outs[f] + base) = o;
        }
    }
}

// ---------------------------------------------------------------------------
// WKV6 linear recurrence with 4-stage cp.async pipeline.
// grid = 128 blocks: (b, h, i-half). 128 threads = 4 warps.
// Warp q owns state rows j in [q*16, q*16+16); lane = local output index i.
// Stage layout (floats): [0:64) r, [64:128) k, [128:192) w, [192:224) v-half.
// ---------------------------------------------------------------------------
#define WKV_DEPTH 4
#define STG_F 224

__global__ __launch_bounds__(128)
void wkv_kernel(const float* __restrict__ rg, const float* __restrict__ kg,
                const float* __restrict__ vg, const float* __restrict__ wg,
                const float* __restrict__ u, float* __restrict__ y)
{
    int bid  = blockIdx.x;
    int ih   = bid & 1;
    int h    = (bid >> 1) & 7;
    int b    = bid >> 4;
    int tid  = threadIdx.x;
    int lane = tid & 31;
    int warp = tid >> 5;

    __shared__ __align__(16) float stg[WKV_DEPTH][STG_F];
    __shared__ float part[4][32];

    float S[16];
#pragma unroll
    for (int jj = 0; jj < 16; jj++) S[jj] = 0.f;

    float uu[16];
#pragma unroll
    for (int jj = 0; jj < 16; jj++) uu[jj] = u[h * 64 + warp * 16 + jj];

    const int hbase = h * 64;

    // cp.async refill of one stage for timestep tt (56 chunks of 16B)
    auto refill = [&](int slot, int tt) {
        if (tid < 56) {
            size_t gbase = (size_t)(b * Tc + tt) * Cc + hbase;
            const float* src;
            float* dst;
            if (tid < 16)      { src = rg + gbase + tid * 4;                dst = &stg[slot][tid * 4]; }
            else if (tid < 32) { src = kg + gbase + (tid - 16) * 4;         dst = &stg[slot][64 + (tid - 16) * 4]; }
            else if (tid < 48) { src = wg + gbase + (tid - 32) * 4;         dst = &stg[slot][128 + (tid - 32) * 4]; }
            else               { src = vg + gbase + ih * 32 + (tid - 48) * 4; dst = &stg[slot][192 + (tid - 48) * 4]; }
            uint32_t da = (uint32_t)__cvta_generic_to_shared(dst);
            asm volatile("cp.async.cg.shared.global [%0], [%1], 16;" :: "r"(da), "l"(src));
        }
        asm volatile("cp.async.commit_group;");
    };

    // prologue: fill all stages
#pragma unroll
    for (int p = 0; p < WKV_DEPTH; p++) refill(p, p);
    asm volatile("cp.async.wait_group %0;" :: "n"(WKV_DEPTH - 2));
    __syncthreads();

    for (int t = 0; t < Tc; t++) {
        int s = t & (WKV_DEPTH - 1);
        const float* st = &stg[s][0];

        float vi = st[192 + lane];
        float y0 = 0.f, y1 = 0.f;
#pragma unroll
        for (int q = 0; q < 4; q++) {
            int j = warp * 16 + q * 4;
            float4 r4 = *reinterpret_cast<const float4*>(st + j);
            float4 k4 = *reinterpret_cast<const float4*>(st + 64 + j);
            float4 w4 = *reinterpret_cast<const float4*>(st + 128 + j);
            float kv, acc;
            kv = k4.x * vi; acc = fmaf(uu[q*4+0], kv, S[q*4+0]); y0 = fmaf(r4.x, acc, y0); S[q*4+0] = fmaf(w4.x, S[q*4+0], kv);
            kv = k4.y * vi; acc = fmaf(uu[q*4+1], kv, S[q*4+1]); y1 = fmaf(r4.y, acc, y1); S[q*4+1] = fmaf(w4.y, S[q*4+1], kv);
            kv = k4.z * vi; acc = fmaf(uu[q*4+2], kv, S[q*4+2]); y0 = fmaf(r4.z, acc, y0); S[q*4+2] = fmaf(w4.z, S[q*4+2], kv);
            kv = k4.w * vi; acc = fmaf(uu[q*4+3], kv, S[q*4+3]); y1 = fmaf(r4.w, acc, y1); S[q*4+3] = fmaf(w4.w, S[q*4+3], kv);
        }
        part[warp][lane] = y0 + y1;
        __syncthreads();          // part ready; all reads of stage[s] done

        if (tid < 32) {
            float yv = (part[0][tid] + part[1][tid]) + (part[2][tid] + part[3][tid]);
            y[(size_t)(b * Tc + t) * Cc + hbase + ih * 32 + tid] = yv;
        }
        if (t + WKV_DEPTH < Tc) refill(s, t + WKV_DEPTH);
        else                    asm volatile("cp.async.commit_group;");
        asm volatile("cp.async.wait_group %0;" :: "n"(WKV_DEPTH - 2));
        __syncthreads();          // next stage visible to all threads; part reusable
    }
}

// ---------------------------------------------------------------------------
// GroupNorm (H groups of N=64) + ln scale/shift + gate multiply
// ---------------------------------------------------------------------------
__global__ __launch_bounds__(256)
void gn_kernel(const float* __restrict__ y, const float* __restrict__ gsrc,
               const float* __restrict__ lng, const float* __restrict__ lnb,
               float* __restrict__ z)
{
    int warp = threadIdx.x >> 5, lane = threadIdx.x & 31;
    int grp = blockIdx.x * 8 + warp;           // < BT*H
    int tg = grp >> 3, h = grp & 7;
    size_t base = (size_t)tg * Cc + h * 64;

    float y0 = y[base + lane];
    float y1 = y[base + 32 + lane];
    float s  = y0 + y1;
    float ss = y0 * y0 + y1 * y1;
#pragma unroll
    for (int o = 16; o; o >>= 1) {
        s  += __shfl_xor_sync(0xffffffffu, s, o);
        ss += __shfl_xor_sync(0xffffffffu, ss, o);
    }
    float mean = s * (1.f / 64.f);
    float var  = ss * (1.f / 64.f) - mean * mean;
    float rstd = rsqrtf(var + 1e-5f);

    int c0 = h * 64 + lane;
    float z0 = fmaf((y0 - mean) * rstd, lng[c0],      lnb[c0]);
    float z1 = fmaf((y1 - mean) * rstd, lng[c0 + 32], lnb[c0 + 32]);
    z[base + lane]      = z0 * gsrc[base + lane];
    z[base + 32 + lane] = z1 * gsrc[base + 32 + lane];
}

// ---------------------------------------------------------------------------
// Launch
// ---------------------------------------------------------------------------
template <typename T>
static float* devptr(T& sym)
{
    void* p = nullptr;
    cudaGetSymbolAddress(&p, sym);
    return (float*)p;
}

extern "C" void kernel_launch(void* const* d_in, const int* in_sizes, int n_in,
                              void* d_out, int out_size)
{
    const float* x      = (const float*)d_in[0];
    const float* maa_x  = (const float*)d_in[1];
    const float* maa_w  = (const float*)d_in[2];
    const float* maa_k  = (const float*)d_in[3];
    const float* maa_v  = (const float*)d_in[4];
    const float* maa_r  = (const float*)d_in[5];
    const float* maa_g  = (const float*)d_in[6];
    const float* W1     = (const float*)d_in[7];   // [512,160]
    const float* W2     = (const float*)d_in[8];   // [5,32,512]
    const float* tdec   = (const float*)d_in[9];   // [512]
    const float* dw1    = (const float*)d_in[10];  // [512,64]
    const float* dw2    = (const float*)d_in[11];  // [64,512]
    const float* faaaa  = (const float*)d_in[12];  // [8,64]
    const float* Wr     = (const float*)d_in[13];
    const float* Wk     = (const float*)d_in[14];
    const float* Wv     = (const float*)d_in[15];
    const float* Wg     = (const float*)d_in[16];
    const float* Wo     = (const float*)d_in[17];
    const float* ln_g   = (const float*)d_in[18];
    const float* ln_b   = (const float*)d_in[19];
    float* out = (float*)d_out;

    float* p_xx   = devptr(g_xx);
    float* p_xxx  = devptr(g_xxx);
    float* p_h    = devptr(g_h);
    float* p_xw   = devptr(g_xw);
    float* p_xk   = devptr(g_xk);
    float* p_xv   = devptr(g_xv);
    float* p_xr   = devptr(g_xr);
    float* p_xg   = devptr(g_xg);
    float* p_r    = devptr(g_r);
    float* p_k    = devptr(g_k);
    float* p_v    = devptr(g_v);
    float* p_gate = devptr(g_gate);
    float* p_wp   = devptr(g_wp);
    float* p_w    = devptr(g_w);
    float* p_y    = devptr(g_y);
    float* p_z    = devptr(g_z);
    float* p_w1t  = devptr(g_w1t);
    float* p_dw1t = devptr(g_dw1t);
    float* p_dw2t = devptr(g_dw2t);

    const int ewGrid = (BTC + 255) / 256;

    // 0) weight transposes (tiny)
    transpose_pad<<<(256*512 + 128*512 + 512*64) / 256, 256>>>(
        W1, dw1, dw2, p_w1t, p_dw1t, p_dw2t);

    // 1) token shift + xxx
    ew_shift_mix<<<ewGrid, 256>>>(x, maa_x, p_xx, p_xxx);

    // 2) h = tanh(xxx @ W1)   [16384,160]  (tf32, N padded to 256)
    {
        dim3 grid(2, BT / 128);
        tf32_gemm<<<grid, 256>>>(p_xxx, p_w1t, p_h, nullptr, BT, Cc, 160, 160, 1);
    }
    // 3) fused: x_f = x + xx*(maa_f + h[:,f] @ W2[f]) for f in {w,k,v,r,g}
    {
        dim3 grid(Cc / 64, BT / 64);
        mix5_kernel<<<grid, 256>>>(p_h, W2, maa_w, maa_k, maa_v, maa_r, maa_g,
                                   x, p_xx, p_xw, p_xk, p_xv, p_xr, p_xg);
    }

    // 4) projections r, k, v, g  (tf32, batched single launch)
    {
        dim3 grid(Cc / 128, BT / 128, 4);
        proj4_kernel<<<grid, 256>>>(p_xr, p_xk, p_xv, p_xg,
                                    Wr, Wk, Wv, Wg,
                                    p_r, p_k, p_v, p_gate);
    }
    // 5) decay path (tf32): wp = tanh(xw @ dw1);  w = exp(-exp(tdec + wp @ dw2))
    {
        dim3 grid1(1, BT / 128);
        tf32_gemm<<<grid1, 256>>>(p_xw, p_dw1t, p_wp, nullptr, BT, Cc, 64, 64, 1);
        dim3 grid2(4, BT / 128);
        tf32_gemm<<<grid2, 256>>>(p_wp, p_dw2t, p_w, tdec, BT, 64, Cc, Cc, 3);
    }

    // 6) WKV6 recurrence (cp.async pipelined)
    wkv_kernel<<<Bc * Hc * 2, 128>>>(p_r, p_k, p_v, p_w, faaaa, p_y);

    // 7) GroupNorm + gate
    gn_kernel<<<(BT * Hc) / 8, 256>>>(p_y, p_gate, ln_g, ln_b, p_z);

    // 8) out = z @ Wo^T  (tf32)
    {
        dim3 grid(4, BT / 128);
        tf32_gemm<<<grid, 256>>>(p_z, Wo, out, nullptr, BT, Cc, Cc, Cc, 0);
    }
}

// round 8
// speedup vs baseline: 1.7679x; 1.0932x over previous
#include <cuda_runtime.h>
#include <cuda_bf16.h>
#include <math.h>
#include <stdint.h>

// Problem constants
#define Bc   8
#define Tc   2048
#define Cc   512
#define Hc   8
#define Nc   64
#define DMIX 32
#define DDEC 64
#define BT   (Bc*Tc)           // 16384
#define BTC  (BT*Cc)           // 8388608

// ---------------------------------------------------------------------------
// Scratch (static device globals; no allocation allowed)
// ---------------------------------------------------------------------------
__device__ float g_xx  [BTC];
__device__ float g_xxx [BTC];
__device__ float g_h   [BT*160];
__device__ float g_xw  [BTC];
__device__ float g_xk  [BTC];
__device__ float g_xv  [BTC];
__device__ float g_xr  [BTC];
__device__ float g_xg  [BTC];
__device__ float g_r   [BTC];
__device__ float g_k   [BTC];
__device__ float g_v   [BTC];
__device__ float g_gate[BTC];
__device__ float g_wp  [BT*DDEC];
__device__ float g_w   [BTC];
__device__ float g_y   [BTC];
__device__ float g_z   [BTC];
__device__ float g_w1t [256*512];   // W1^T padded 160->256 rows
__device__ float g_dw1t[128*512];   // dw1^T padded 64->128 rows
__device__ float g_dw2t[512*64];    // dw2^T [512][64]

// ---------------------------------------------------------------------------
// Elementwise: token shift + xxx = x + xx * maa_x
// ---------------------------------------------------------------------------
__global__ void ew_shift_mix(const float* __restrict__ x,
                             const float* __restrict__ maa_x,
                             float* __restrict__ xx, float* __restrict__ xxx)
{
    int idx = blockIdx.x * 256 + threadIdx.x;
    if (idx >= BTC) return;
    int c  = idx & (Cc - 1);
    int tg = idx >> 9;
    int tt = tg & (Tc - 1);
    float xi = x[idx];
    float xs = (tt > 0) ? x[idx - Cc] : 0.f;
    float xxv = xs - xi;
    xx[idx]  = xxv;
    xxx[idx] = fmaf(xxv, maa_x[c], xi);
}

// ---------------------------------------------------------------------------
// Weight transpose + zero-pad (tiny, once per call)
// ---------------------------------------------------------------------------
__global__ void transpose_pad(const float* __restrict__ W1,
                              const float* __restrict__ dw1,
                              const float* __restrict__ dw2,
                              float* __restrict__ w1t,
                              float* __restrict__ dw1t,
                              float* __restrict__ dw2t)
{
    int idx = blockIdx.x * 256 + threadIdx.x;
    if (idx < 256 * 512) {
        int n = idx >> 9, k = idx & 511;
        w1t[idx] = (n < 160) ? W1[k * 160 + n] : 0.f;
    } else if (idx < 256 * 512 + 128 * 512) {
        int j = idx - 256 * 512;
        int n = j >> 9, k = j & 511;
        dw1t[j] = (n < 64) ? dw1[k * 64 + n] : 0.f;
    } else if (idx < 256 * 512 + 128 * 512 + 512 * 64) {
        int j = idx - (256 * 512 + 128 * 512);
        int n = j >> 6, k = j & 63;
        dw2t[j] = dw2[k * 512 + n];
    }
}

// ---------------------------------------------------------------------------
// TF32 tensor-core GEMM: C[M,Nreal] = epi( A[M,K] @ W[Npad,K]^T )
//   cp.async 2-stage static-smem double buffer (40KB, no dynamic smem,
//   no cudaFuncSetAttribute). cvt to tf32 on fragment load.
//   epi: 0 none, 1 tanh, 2 silu, 3 exp(-exp(bias[n]+v))
// ---------------------------------------------------------------------------
__device__ __forceinline__ uint32_t f2tf32(float x)
{
    uint32_t u;
    asm("cvt.rna.tf32.f32 %0, %1;" : "=r"(u) : "f"(x));
    return u;
}

__device__ __forceinline__ void tf32_body(const float* __restrict__ A,
                                          const float* __restrict__ W,
                                          float* __restrict__ Cm,
                                          const float* __restrict__ bias,
                                          int M, int K, int Nreal, int ldc, int epi)
{
    __shared__ float As[2][128][20];
    __shared__ float Bs[2][128][20];

    int tid  = threadIdx.x;
    int warp = tid >> 5, lane = tid & 31;
    int wm = (warp >> 2) * 64;
    int wn = (warp & 3) * 32;
    int gid = lane >> 2, tig = lane & 3;
    int m0 = blockIdx.y * 128, n0 = blockIdx.x * 128;

    int lr = tid >> 1;
    int lq = (tid & 1) * 2;
    const float* Aptr = A + (size_t)(m0 + lr) * K;
    const float* Wptr = W + (size_t)(n0 + lr) * K;

    float acc[4][4][4];
#pragma unroll
    for (int mt = 0; mt < 4; mt++)
#pragma unroll
        for (int nt = 0; nt < 4; nt++)
#pragma unroll
            for (int d = 0; d < 4; d++) acc[mt][nt][d] = 0.f;

    auto stage = [&](int buf, int k0) {
#pragma unroll
        for (int i = 0; i < 2; i++) {
            int kq = (lq + i) * 4;
            uint32_t da = (uint32_t)__cvta_generic_to_shared(&As[buf][lr][kq]);
            asm volatile("cp.async.cg.shared.global [%0], [%1], 16;"
                         :: "r"(da), "l"(Aptr + k0 + kq));
            uint32_t db = (uint32_t)__cvta_generic_to_shared(&Bs[buf][lr][kq]);
            asm volatile("cp.async.cg.shared.global [%0], [%1], 16;"
                         :: "r"(db), "l"(Wptr + k0 + kq));
        }
        asm volatile("cp.async.commit_group;");
    };

    int ntiles = K >> 4;
    stage(0, 0);
    if (ntiles > 1) stage(1, 16); else asm volatile("cp.async.commit_group;");
    asm volatile("cp.async.wait_group 1;");   // tile 0 resident, tile 1 in flight
    __syncthreads();

    for (int i = 0; i < ntiles; i++) {
        int buf = i & 1;

#pragma unroll
        for (int ks = 0; ks < 2; ks++) {
            int kb = ks * 8;
            uint32_t afr[4][4];
#pragma unroll
            for (int mt = 0; mt < 4; mt++) {
                int m = wm + mt * 16;
                afr[mt][0] = f2tf32(As[buf][m + gid    ][kb + tig    ]);
                afr[mt][1] = f2tf32(As[buf][m + gid + 8][kb + tig    ]);
                afr[mt][2] = f2tf32(As[buf][m + gid    ][kb + tig + 4]);
                afr[mt][3] = f2tf32(As[buf][m + gid + 8][kb + tig + 4]);
            }
            uint32_t bfr[4][2];
#pragma unroll
            for (int nt = 0; nt < 4; nt++) {
                int n = wn + nt * 8;
                bfr[nt][0] = f2tf32(Bs[buf][n + gid][kb + tig    ]);
                bfr[nt][1] = f2tf32(Bs[buf][n + gid][kb + tig + 4]);
            }
#pragma unroll
            for (int mt = 0; mt < 4; mt++)
#pragma unroll
                for (int nt = 0; nt < 4; nt++) {
                    asm volatile(
                        "mma.sync.aligned.m16n8k8.row.col.f32.tf32.tf32.f32 "
                        "{%0,%1,%2,%3}, {%4,%5,%6,%7}, {%8,%9}, {%0,%1,%2,%3};"
                        : "+f"(acc[mt][nt][0]), "+f"(acc[mt][nt][1]),
                          "+f"(acc[mt][nt][2]), "+f"(acc[mt][nt][3])
                        : "r"(afr[mt][0]), "r"(afr[mt][1]),
                          "r"(afr[mt][2]), "r"(afr[mt][3]),
                          "r"(bfr[nt][0]), "r"(bfr[nt][1]));
                }
        }

        __syncthreads();  // done reading buf; safe to overwrite
        if (i + 2 < ntiles) stage(buf, (i + 2) * 16);
        else                asm volatile("cp.async.commit_group;");
        asm volatile("cp.async.wait_group 1;");   // tile i+1 resident
        __syncthreads();
    }

#pragma unroll
    for (int mt = 0; mt < 4; mt++) {
        int m = m0 + wm + mt * 16 + gid;
#pragma unroll
        for (int nt = 0; nt < 4; nt++) {
            int gb = n0 + wn + nt * 8;       // 8-col group base; Nreal % 8 == 0
            if (gb >= Nreal) continue;
            int n = gb + 2 * tig;
            float v0 = acc[mt][nt][0], v1 = acc[mt][nt][1];
            float v2 = acc[mt][nt][2], v3 = acc[mt][nt][3];
            if (epi == 1) {
                v0 = tanhf(v0); v1 = tanhf(v1); v2 = tanhf(v2); v3 = tanhf(v3);
            } else if (epi == 2) {
                v0 = v0 / (1.f + expf(-v0));
                v1 = v1 / (1.f + expf(-v1));
                v2 = v2 / (1.f + expf(-v2));
                v3 = v3 / (1.f + expf(-v3));
            } else if (epi == 3) {
                float b0 = bias[n], b1 = bias[n + 1];
                v0 = expf(-expf(b0 + v0));
                v1 = expf(-expf(b1 + v1));
                v2 = expf(-expf(b0 + v2));
                v3 = expf(-expf(b1 + v3));
            }
            *reinterpret_cast<float2*>(&Cm[(size_t)m * ldc + n])       = make_float2(v0, v1);
            *reinterpret_cast<float2*>(&Cm[(size_t)(m + 8) * ldc + n]) = make_float2(v2, v3);
        }
    }
}

__global__ __launch_bounds__(256)
void tf32_gemm(const float* __restrict__ A, const float* __restrict__ W,
               float* __restrict__ C, const float* __restrict__ bias,
               int M, int K, int Nreal, int ldc, int epi)
{
    tf32_body(A, W, C, bias, M, K, Nreal, ldc, epi);
}

// 4 projections in one launch (blockIdx.z selects)
__global__ __launch_bounds__(256)
void proj4_kernel(const float* __restrict__ xr, const float* __restrict__ xk,
                  const float* __restrict__ xv, const float* __restrict__ xg,
                  const float* __restrict__ Wr, const float* __restrict__ Wk,
                  const float* __restrict__ Wv, const float* __restrict__ Wg,
                  float* __restrict__ r, float* __restrict__ k,
                  float* __restrict__ v, float* __restrict__ g)
{
    const float* A; const float* W; float* C; int epi = 0;
    int z = blockIdx.z;
    if      (z == 0) { A = xr; W = Wr; C = r; }
    else if (z == 1) { A = xk; W = Wk; C = k; }
    else if (z == 2) { A = xv; W = Wv; C = v; }
    else             { A = xg; W = Wg; C = g; epi = 2; }
    tf32_body(A, W, C, nullptr, BT, Cc, Cc, Cc, epi);
}

// ---------------------------------------------------------------------------
// Fused 5-way mix GEMM (unchanged)
// ---------------------------------------------------------------------------
__global__ __launch_bounds__(256)
void mix5_kernel(const float* __restrict__ hsrc, const float* __restrict__ W2,
                 const float* __restrict__ m0p, const float* __restrict__ m1p,
                 const float* __restrict__ m2p, const float* __restrict__ m3p,
                 const float* __restrict__ m4p,
                 const float* __restrict__ x, const float* __restrict__ xx,
                 float* __restrict__ o0, float* __restrict__ o1,
                 float* __restrict__ o2, float* __restrict__ o3,
                 float* __restrict__ o4)
{
    __shared__ float As[32][68];
    __shared__ float Bs[32][68];

    int tid = threadIdx.x;
    int tx = tid & 15, ty = tid >> 4;
    int m0 = blockIdx.y * 64;
    int n0 = blockIdx.x * 64;

    float acc[5][4][4];
#pragma unroll
    for (int f = 0; f < 5; f++)
#pragma unroll
        for (int i = 0; i < 4; i++)
#pragma unroll
            for (int j = 0; j < 4; j++) acc[f][i][j] = 0.f;

    int arow = tid >> 2;
    int aq   = (tid & 3) * 2;
    int brow = tid >> 3;
    int bq   = (tid & 7) * 8;

    for (int f = 0; f < 5; f++) {
        __syncthreads();
        {
            const float* ap = hsrc + (size_t)(m0 + arow) * 160 + f * 32;
#pragma unroll
            for (int i = 0; i < 2; i++) {
                int col = (aq + i) * 4;
                float4 av = *reinterpret_cast<const float4*>(ap + col);
                As[col + 0][arow] = av.x;
                As[col + 1][arow] = av.y;
                As[col + 2][arow] = av.z;
                As[col + 3][arow] = av.w;
            }
        }
        {
            const float* bp = W2 + (size_t)f * 32 * Cc + (size_t)brow * Cc + n0 + bq;
            *reinterpret_cast<float4*>(&Bs[brow][bq])     = *reinterpret_cast<const float4*>(bp);
            *reinterpret_cast<float4*>(&Bs[brow][bq + 4]) = *reinterpret_cast<const float4*>(bp + 4);
        }
        __syncthreads();

#pragma unroll
        for (int kk = 0; kk < 32; kk++) {
            float4 a4 = *reinterpret_cast<const float4*>(&As[kk][ty * 4]);
            float4 b4 = *reinterpret_cast<const float4*>(&Bs[kk][tx * 4]);
            float ar[4] = {a4.x, a4.y, a4.z, a4.w};
            float br[4] = {b4.x, b4.y, b4.z, b4.w};
#pragma unroll
            for (int i = 0; i < 4; i++)
#pragma unroll
                for (int j = 0; j < 4; j++)
                    acc[f][i][j] = fmaf(ar[i], br[j], acc[f][i][j]);
        }
    }

    int nb = n0 + tx * 4;
    float4 ma[5];
    ma[0] = *reinterpret_cast<const float4*>(m0p + nb);
    ma[1] = *reinterpret_cast<const float4*>(m1p + nb);
    ma[2] = *reinterpret_cast<const float4*>(m2p + nb);
    ma[3] = *reinterpret_cast<const float4*>(m3p + nb);
    ma[4] = *reinterpret_cast<const float4*>(m4p + nb);
    float* outs[5] = {o0, o1, o2, o3, o4};

#pragma unroll
    for (int i = 0; i < 4; i++) {
        size_t base = (size_t)(m0 + ty * 4 + i) * Cc + nb;
        float4 xv  = *reinterpret_cast<const float4*>(x + base);
        float4 xxv = *reinterpret_cast<const float4*>(xx + base);
#pragma unroll
        for (int f = 0; f < 5; f++) {
            float4 o;
            o.x = fmaf(xxv.x, ma[f].x + acc[f][i][0], xv.x);
            o.y = fmaf(xxv.y, ma[f].y + acc[f][i][1], xv.y);
            o.z = fmaf(xxv.z, ma[f].z + acc[f][i][2], xv.z);
            o.w = fmaf(xxv.w, ma[f].w + acc[f][i][3], xv.w);
            *reinterpret_cast<float4*>(outs[f] + base) = o;
        }
    }
}

// ---------------------------------------------------------------------------
// WKV6 linear recurrence, 4-stage cp.async ring, 2 timesteps per barrier pair.
// grid = 128 blocks: (b, h, i-half). 128 threads = 4 warps.
// Stage layout (floats): [0:64) r, [64:128) k, [128:192) w, [192:224) v-half.
// ---------------------------------------------------------------------------
#define WKV_DEPTH 4
#define STG_F 224

__global__ __launch_bounds__(128)
void wkv_kernel(const float* __restrict__ rg, const float* __restrict__ kg,
                const float* __restrict__ vg, const float* __restrict__ wg,
                const float* __restrict__ u, float* __restrict__ y)
{
    int bid  = blockIdx.x;
    int ih   = bid & 1;
    int h    = (bid >> 1) & 7;
    int b    = bid >> 4;
    int tid  = threadIdx.x;
    int lane = tid & 31;
    int warp = tid >> 5;

    __shared__ __align__(16) float stg[WKV_DEPTH][STG_F];
    __shared__ float part[2][4][32];

    float S[16];
#pragma unroll
    for (int jj = 0; jj < 16; jj++) S[jj] = 0.f;

    float uu[16];
#pragma unroll
    for (int jj = 0; jj < 16; jj++) uu[jj] = u[h * 64 + warp * 16 + jj];

    const int hbase = h * 64;

    auto refill = [&](int slot, int tt) {
        if (tid < 56) {
            size_t gbase = (size_t)(b * Tc + tt) * Cc + hbase;
            const float* src;
            float* dst;
            if (tid < 16)      { src = rg + gbase + tid * 4;                  dst = &stg[slot][tid * 4]; }
            else if (tid < 32) { src = kg + gbase + (tid - 16) * 4;           dst = &stg[slot][64 + (tid - 16) * 4]; }
            else if (tid < 48) { src = wg + gbase + (tid - 32) * 4;           dst = &stg[slot][128 + (tid - 32) * 4]; }
            else               { src = vg + gbase + ih * 32 + (tid - 48) * 4; dst = &stg[slot][192 + (tid - 48) * 4]; }
            uint32_t da = (uint32_t)__cvta_generic_to_shared(dst);
            asm volatile("cp.async.cg.shared.global [%0], [%1], 16;" :: "r"(da), "l"(src));
        }
        asm volatile("cp.async.commit_group;");
    };

    auto step = [&](const float* st, int pslot) {
        float vi = st[192 + lane];
        float y0 = 0.f, y1 = 0.f;
#pragma unroll
        for (int q = 0; q < 4; q++) {
            int j = warp * 16 + q * 4;
            float4 r4 = *reinterpret_cast<const float4*>(st + j);
            float4 k4 = *reinterpret_cast<const float4*>(st + 64 + j);
            float4 w4 = *reinterpret_cast<const float4*>(st + 128 + j);
            float kv, acc;
            kv = k4.x * vi; acc = fmaf(uu[q*4+0], kv, S[q*4+0]); y0 = fmaf(r4.x, acc, y0); S[q*4+0] = fmaf(w4.x, S[q*4+0], kv);
            kv = k4.y * vi; acc = fmaf(uu[q*4+1], kv, S[q*4+1]); y1 = fmaf(r4.y, acc, y1); S[q*4+1] = fmaf(w4.y, S[q*4+1], kv);
            kv = k4.z * vi; acc = fmaf(uu[q*4+2], kv, S[q*4+2]); y0 = fmaf(r4.z, acc, y0); S[q*4+2] = fmaf(w4.z, S[q*4+2], kv);
            kv = k4.w * vi; acc = fmaf(uu[q*4+3], kv, S[q*4+3]); y1 = fmaf(r4.w, acc, y1); S[q*4+3] = fmaf(w4.w, S[q*4+3], kv);
        }
        part[pslot][warp][lane] = y0 + y1;
    };

    // prologue: fill all 4 stages
#pragma unroll
    for (int p = 0; p < WKV_DEPTH; p++) refill(p, p);
    asm volatile("cp.async.wait_group 2;");   // stages 0,1 ready
    __syncthreads();

    for (int t = 0; t < Tc; t += 2) {
        int s0 = t & 3, s1 = (t + 1) & 3;
        step(&stg[s0][0], 0);
        step(&stg[s1][0], 1);
        __syncthreads();      // parts ready; stages s0,s1 fully consumed

        if (tid < 32) {
            size_t yb = (size_t)(b * Tc + t) * Cc + hbase + ih * 32 + tid;
            float ya  = (part[0][0][tid] + part[0][1][tid]) + (part[0][2][tid] + part[0][3][tid]);
            float ybv = (part[1][0][tid] + part[1][1][tid]) + (part[1][2][tid] + part[1][3][tid]);
            y[yb]      = ya;
            y[yb + Cc] = ybv;
        }
        if (t + 4 < Tc) refill(s0, t + 4);
        else            asm volatile("cp.async.commit_group;");
        if (t + 5 < Tc) refill(s1, t + 5);
        else            asm volatile("cp.async.commit_group;");
        asm volatile("cp.async.wait_group 2;");  // stages t+2, t+3 complete
        __syncthreads();
    }
}

// ---------------------------------------------------------------------------
// GroupNorm (H groups of N=64) + ln scale/shift + gate multiply
// ---------------------------------------------------------------------------
__global__ __launch_bounds__(256)
void gn_kernel(const float* __restrict__ y, const float* __restrict__ gsrc,
               const float* __restrict__ lng, const float* __restrict__ lnb,
               float* __restrict__ z)
{
    int warp = threadIdx.x >> 5, lane = threadIdx.x & 31;
    int grp = blockIdx.x * 8 + warp;           // < BT*H
    int tg = grp >> 3, h = grp & 7;
    size_t base = (size_t)tg * Cc + h * 64;

    float y0 = y[base + lane];
    float y1 = y[base + 32 + lane];
    float s  = y0 + y1;
    float ss = y0 * y0 + y1 * y1;
#pragma unroll
    for (int o = 16; o; o >>= 1) {
        s  += __shfl_xor_sync(0xffffffffu, s, o);
        ss += __shfl_xor_sync(0xffffffffu, ss, o);
    }
    float mean = s * (1.f / 64.f);
    float var  = ss * (1.f / 64.f) - mean * mean;
    float rstd = rsqrtf(var + 1e-5f);

    int c0 = h * 64 + lane;
    float z0 = fmaf((y0 - mean) * rstd, lng[c0],      lnb[c0]);
    float z1 = fmaf((y1 - mean) * rstd, lng[c0 + 32], lnb[c0 + 32]);
    z[base + lane]      = z0 * gsrc[base + lane];
    z[base + 32 + lane] = z1 * gsrc[base + 32 + lane];
}

// ---------------------------------------------------------------------------
// Launch
// ---------------------------------------------------------------------------
template <typename T>
static float* devptr(T& sym)
{
    void* p = nullptr;
    cudaGetSymbolAddress(&p, sym);
    return (float*)p;
}

extern "C" void kernel_launch(void* const* d_in, const int* in_sizes, int n_in,
                              void* d_out, int out_size)
{
    const float* x      = (const float*)d_in[0];
    const float* maa_x  = (const float*)d_in[1];
    const float* maa_w  = (const float*)d_in[2];
    const float* maa_k  = (const float*)d_in[3];
    const float* maa_v  = (const float*)d_in[4];
    const float* maa_r  = (const float*)d_in[5];
    const float* maa_g  = (const float*)d_in[6];
    const float* W1     = (const float*)d_in[7];   // [512,160]
    const float* W2     = (const float*)d_in[8];   // [5,32,512]
    const float* tdec   = (const float*)d_in[9];   // [512]
    const float* dw1    = (const float*)d_in[10];  // [512,64]
    const float* dw2    = (const float*)d_in[11];  // [64,512]
    const float* faaaa  = (const float*)d_in[12];  // [8,64]
    const float* Wr     = (const float*)d_in[13];
    const float* Wk     = (const float*)d_in[14];
    const float* Wv     = (const float*)d_in[15];
    const float* Wg     = (const float*)d_in[16];
    const float* Wo     = (const float*)d_in[17];
    const float* ln_g   = (const float*)d_in[18];
    const float* ln_b   = (const float*)d_in[19];
    float* out = (float*)d_out;

    float* p_xx   = devptr(g_xx);
    float* p_xxx  = devptr(g_xxx);
    float* p_h    = devptr(g_h);
    float* p_xw   = devptr(g_xw);
    float* p_xk   = devptr(g_xk);
    float* p_xv   = devptr(g_xv);
    float* p_xr   = devptr(g_xr);
    float* p_xg   = devptr(g_xg);
    float* p_r    = devptr(g_r);
    float* p_k    = devptr(g_k);
    float* p_v    = devptr(g_v);
    float* p_gate = devptr(g_gate);
    float* p_wp   = devptr(g_wp);
    float* p_w    = devptr(g_w);
    float* p_y    = devptr(g_y);
    float* p_z    = devptr(g_z);
    float* p_w1t  = devptr(g_w1t);
    float* p_dw1t = devptr(g_dw1t);
    float* p_dw2t = devptr(g_dw2t);

    const int ewGrid = (BTC + 255) / 256;

    // 0) weight transposes (tiny)
    transpose_pad<<<(256*512 + 128*512 + 512*64) / 256, 256>>>(
        W1, dw1, dw2, p_w1t, p_dw1t, p_dw2t);

    // 1) token shift + xxx
    ew_shift_mix<<<ewGrid, 256>>>(x, maa_x, p_xx, p_xxx);

    // 2) h = tanh(xxx @ W1)   [16384,160]  (tf32, N padded to 256)
    {
        dim3 grid(2, BT / 128);
        tf32_gemm<<<grid, 256>>>(p_xxx, p_w1t, p_h, nullptr, BT, Cc, 160, 160, 1);
    }
    // 3) fused: x_f = x + xx*(maa_f + h[:,f] @ W2[f]) for f in {w,k,v,r,g}
    {
        dim3 grid(Cc / 64, BT / 64);
        mix5_kernel<<<grid, 256>>>(p_h, W2, maa_w, maa_k, maa_v, maa_r, maa_g,
                                   x, p_xx, p_xw, p_xk, p_xv, p_xr, p_xg);
    }

    // 4) projections r, k, v, g  (tf32, batched single launch)
    {
        dim3 grid(Cc / 128, BT / 128, 4);
        proj4_kernel<<<grid, 256>>>(p_xr, p_xk, p_xv, p_xg,
                                    Wr, Wk, Wv, Wg,
                                    p_r, p_k, p_v, p_gate);
    }
    // 5) decay path (tf32): wp = tanh(xw @ dw1);  w = exp(-exp(tdec + wp @ dw2))
    {
        dim3 grid1(1, BT / 128);
        tf32_gemm<<<grid1, 256>>>(p_xw, p_dw1t, p_wp, nullptr, BT, Cc, 64, 64, 1);
        dim3 grid2(4, BT / 128);
        tf32_gemm<<<grid2, 256>>>(p_wp, p_dw2t, p_w, tdec, BT, 64, Cc, Cc, 3);
    }

    // 6) WKV6 recurrence (cp.async pipelined, 2-step unroll)
    wkv_kernel<<<Bc * Hc * 2, 128>>>(p_r, p_k, p_v, p_w, faaaa, p_y);

    // 7) GroupNorm + gate
    gn_kernel<<<(BT * Hc) / 8, 256>>>(p_y, p_gate, ln_g, ln_b, p_z);

    // 8) out = z @ Wo^T  (tf32)
    {
        dim3 grid(4, BT / 128);
        tf32_gemm<<<grid, 256>>>(p_z, Wo, out, nullptr, BT, Cc, Cc, Cc, 0);
    }
}